// round 11
// baseline (speedup 1.0000x reference)
#include <cuda_runtime.h>
#include <cstdint>

#define BB 16
#define HH 96
#define WW 128
#define HWW (HH*WW)          // 12288
#define NPIX (BB*HWW)        // 196608
#define CP 196
#define PH 98                // padded rows   (y+1)
#define PWS 136              // padded stride (x+4)
#define PPL (PH*PWS)         // 13328 floats / channel plane

// ---------------- packed-f32x2 helpers -----------------------------------------
__device__ __forceinline__ unsigned long long pack2(float x, float y) {
    unsigned long long r;
    asm("mov.b64 %0, {%1, %2};" : "=l"(r) : "f"(x), "f"(y));
    return r;
}
__device__ __forceinline__ void ffma2(unsigned long long& acc,
                                      unsigned long long a, unsigned long long b) {
    asm("fma.rn.f32x2 %0, %1, %2, %0;" : "+l"(acc) : "l"(a), "l"(b));
}
__device__ __forceinline__ float2 unpack2(unsigned long long v) {
    float2 f;
    asm("mov.b64 {%0, %1}, %2;" : "=f"(f.x), "=f"(f.y) : "l"(v));
    return f;
}
__device__ __forceinline__ void cp16(uint32_t dst, const void* src) {
    asm volatile("cp.async.cg.shared.global [%0], [%1], 16;" :: "r"(dst), "l"(src));
}
__device__ __forceinline__ float fq(float w, float sc) {
    return fminf(fmaxf(rintf(w / sc), -127.f), 127.f) * sc;
}

// ---------------- device scratch ------------------------------------------------
__device__ unsigned g_scmax[5];                   // maxabs bits per tensor (monotone, idempotent)
// padded activations: zero-initialized BSS; borders NEVER written -> stay zero.
__device__ __align__(16) float g_cfp[(size_t)BB*128*PPL];

// ---------------- 1) quantization scales: one reduce kernel ----------------------
// g_scmax starts 0 (BSS); atomicMax with identical values every replay -> deterministic.
__device__ __forceinline__ void qmap(int bid, int& t, int& start, int& cnt) {
    if      (bid < 32)  { t = 0; start = bid * 588;        cnt = 588;  }
    else if (bid == 32) { t = 1; start = 0;                cnt = 128;  }
    else if (bid == 33) { t = 2; start = 0;                cnt = 2048; }
    else if (bid == 34) { t = 3; start = 0;                cnt = 1152; }
    else                { t = 4; start = (bid - 35) * 2048; cnt = 2048; }
}

__global__ void quant_reduce(const float* __restrict__ Wc1,
                             const float* __restrict__ Wf1,
                             const float* __restrict__ Wf2,
                             const float* __restrict__ Wd,
                             const float* __restrict__ Wp) {
    __shared__ float red[256];
    int t, start, cnt;
    qmap(blockIdx.x, t, start, cnt);
    const float* src = (t==0) ? Wc1 : (t==1) ? Wf1 : (t==2) ? Wf2 : (t==3) ? Wd : Wp;

    float m = 0.f;
    for (int i = threadIdx.x; i < cnt; i += 256) m = fmaxf(m, fabsf(src[start + i]));
    red[threadIdx.x] = m;
    __syncthreads();
    for (int s = 128; s > 0; s >>= 1) {
        if (threadIdx.x < s) red[threadIdx.x] = fmaxf(red[threadIdx.x], red[threadIdx.x+s]);
        __syncthreads();
    }
    if (threadIdx.x == 0) atomicMax(&g_scmax[t], __float_as_uint(red[0]));
}

// ---------------- 2) fused cor (48-ch halves) + flo, inline weight quant ---------
#define KC 14
#define NCHK 14
__global__ __launch_bounds__(256, 3) void corflo_kernel(const float* __restrict__ corr,
                                                        const float* __restrict__ bc1,
                                                        const float* __restrict__ Wc1,
                                                        const float* __restrict__ flow,
                                                        const float* __restrict__ Wf1,
                                                        const float* __restrict__ bf1,
                                                        const float* __restrict__ Wf2,
                                                        const float* __restrict__ bf2) {
    extern __shared__ __align__(16) float sm[];
    const int tid = threadIdx.x;

    if (blockIdx.x >= 1536) {
        // ---------------- flo path ----------------
        float* w1 = sm;            // 128
        float* b1 = sm + 128;      // 64
        float* w2 = sm + 192;      // 2048 [k][32]
        float* b2 = sm + 2240;     // 32
        const float sc1 = fmaxf(__uint_as_float(g_scmax[1]), 1e-8f) / 127.f;
        const float sc2 = fmaxf(__uint_as_float(g_scmax[2]), 1e-8f) / 127.f;
        for (int i = tid; i < 128;  i += 256) w1[i] = fq(Wf1[i], sc1);
        for (int i = tid; i < 64;   i += 256) b1[i] = bf1[i];
        for (int i = tid; i < 2048; i += 256) {
            int k = i >> 5, o = i & 31;
            w2[i] = fq(Wf2[o*64 + k], sc2);
        }
        for (int i = tid; i < 32;   i += 256) b2[i] = bf2[i];
        __syncthreads();

        int p  = (blockIdx.x - 1536) * 256 + tid;
        int b  = p / HWW, hw = p % HWW;
        float fx = flow[(size_t)b * 2 * HWW + hw];
        float fy = flow[(size_t)b * 2 * HWW + HWW + hw];

        unsigned long long acc[16];
        #pragma unroll
        for (int q = 0; q < 16; q++) acc[q] = pack2(b2[2*q], b2[2*q+1]);

        #pragma unroll 4
        for (int j = 0; j < 64; j++) {
            float h = fmaxf(fmaf(fx, w1[2*j], fmaf(fy, w1[2*j+1], b1[j])), 0.f);
            unsigned long long hh = pack2(h, h);
            const ulonglong2* wv = reinterpret_cast<const ulonglong2*>(w2 + j*32);
            #pragma unroll
            for (int q = 0; q < 8; q++) {
                ulonglong2 a = wv[q];
                ffma2(acc[2*q],   hh, a.x);
                ffma2(acc[2*q+1], hh, a.y);
            }
        }

        const int y = hw >> 7, x = hw & 127;
        float* obase = g_cfp + ((size_t)(b*128 + 96) * PH + (y+1)) * PWS + x + 4;
        #pragma unroll
        for (int q = 0; q < 16; q++) {
            float2 f = unpack2(acc[q]);
            obase[(size_t)(2*q)   * PPL] = fmaxf(f.x, 0.f);
            obase[(size_t)(2*q+1) * PPL] = fmaxf(f.y, 0.f);
        }
        return;
    }

    // ---------------- cor path: 48 of 96 channels ----------------
    float* Ws = sm;                    // [196][48] = 9408
    float* bs = Ws + CP*48;            // 48
    float* Xs = bs + 48;               // [2][14][256] = 7168

    const int half = blockIdx.x & 1;
    const int co   = half * 48;
    {
        const float sc0 = fmaxf(__uint_as_float(g_scmax[0]), 1e-8f) / 127.f;
        const float* wsrc = Wc1 + (size_t)co * CP;   // j-major: coalesced reads
        for (int i = tid; i < CP*48; i += 256) {
            int j = i / CP, k = i - j*CP;
            Ws[k*48 + j] = fq(wsrc[i], sc0);
        }
    }
    if (tid < 48) bs[tid] = bc1[co + tid];

    const int tile = blockIdx.x >> 1;
    const int pix0 = tile * 256;
    const int b = pix0 / HWW, hw0 = pix0 % HWW;
    const float* cbase = corr + (size_t)b * CP * HWW + hw0;

    uint32_t xs_s = (uint32_t)__cvta_generic_to_shared(Xs);

    auto issue = [&](int c, int buf) {
        #pragma unroll
        for (int j = 0; j < 4; j++) {          // 14*64 = 896 float4
            int idx = tid + j*256;
            if (idx < 896) {
                int kk = idx >> 6, off = idx & 63;
                cp16(xs_s + (uint32_t)(((buf*KC + kk)*256 + off*4)*4),
                     cbase + (size_t)(c*KC + kk) * HWW + off*4);
            }
        }
        asm volatile("cp.async.commit_group;");
    };

    issue(0, 0);
    __syncthreads();   // Ws/bs visible

    const int po = tid >> 6, pg = tid & 63;    // 4 ch-groups of 12 x 64 pixel-quads

    unsigned long long acc[24];                // [p=4][jj=6] channel pairs
    #pragma unroll
    for (int jj = 0; jj < 6; jj++) {
        unsigned long long bv = pack2(bs[12*po + 2*jj], bs[12*po + 2*jj + 1]);
        acc[jj] = bv; acc[6+jj] = bv; acc[12+jj] = bv; acc[18+jj] = bv;
    }

    for (int c = 0; c < NCHK; c++) {
        if (c + 1 < NCHK) {
            issue(c + 1, (c + 1) & 1);
            asm volatile("cp.async.wait_group 1;");
        } else {
            asm volatile("cp.async.wait_group 0;");
        }
        __syncthreads();
        const float4* xsb = (const float4*)(Xs + (c & 1) * KC * 256);
        const float*  wrb = Ws + c * KC * 48 + 12 * po;
        #pragma unroll
        for (int kk = 0; kk < KC; kk++) {
            float4 xv = xsb[kk*64 + pg];
            unsigned long long x0 = pack2(xv.x, xv.x);
            unsigned long long x1 = pack2(xv.y, xv.y);
            unsigned long long x2 = pack2(xv.z, xv.z);
            unsigned long long x3 = pack2(xv.w, xv.w);
            const ulonglong2* wr = (const ulonglong2*)(wrb + kk*48);
            // b-operand grouped for RF reuse-cache: 4 consecutive FFMA2 share w.x / w.y
            #pragma unroll
            for (int q2 = 0; q2 < 3; q2++) {
                ulonglong2 w = wr[q2];
                ffma2(acc[     2*q2], x0, w.x);
                ffma2(acc[ 6 + 2*q2], x1, w.x);
                ffma2(acc[12 + 2*q2], x2, w.x);
                ffma2(acc[18 + 2*q2], x3, w.x);
                ffma2(acc[     2*q2+1], x0, w.y);
                ffma2(acc[ 6 + 2*q2+1], x1, w.y);
                ffma2(acc[12 + 2*q2+1], x2, w.y);
                ffma2(acc[18 + 2*q2+1], x3, w.y);
            }
        }
        __syncthreads();   // buffer reuse fence
    }

    const int hw = hw0 + 4*pg;
    const int y = hw >> 7, x = hw & 127;
    float* ob = g_cfp + ((size_t)(b*128 + co + 12*po) * PH + (y+1)) * PWS + x + 4;
    #pragma unroll
    for (int jj = 0; jj < 6; jj++) {
        float2 f0 = unpack2(acc[jj]),    f1 = unpack2(acc[6+jj]);
        float2 f2 = unpack2(acc[12+jj]), f3 = unpack2(acc[18+jj]);
        float4 e = make_float4(fmaxf(f0.x,0.f), fmaxf(f1.x,0.f), fmaxf(f2.x,0.f), fmaxf(f3.x,0.f));
        float4 o = make_float4(fmaxf(f0.y,0.f), fmaxf(f1.y,0.f), fmaxf(f2.y,0.f), fmaxf(f3.y,0.f));
        *(float4*)(ob + (size_t)(2*jj)   * PPL) = e;
        *(float4*)(ob + (size_t)(2*jj+1) * PPL) = o;
    }
}

// ---------------- 3) fused dw3x3 + pw 128->80 : phase A/B, inline quant ----------
#define ITB 3456    // floats per halo buffer: 8 ch * 6 rows * 72
#define DWS 260     // dwb channel stride
__global__ __launch_bounds__(256, 2) void dwpw_kernel(const float* __restrict__ flow,
                                                      const float* __restrict__ Wd,
                                                      const float* __restrict__ Wp,
                                                      const float* __restrict__ bp,
                                                      float* __restrict__ out) {
    extern __shared__ __align__(16) float sm2[];
    float* wph = sm2;              // [128][80]  = 10240
    float* wd  = wph + 10240;      // [128][12]  = 1536
    float* bph = wd + 1536;        // 80
    float* it  = bph + 80;         // 2 x [8][6][72] = 6912
    float* dwb = it + 2*ITB;       // [8][260]   = 2080

    const int tid = threadIdx.x;
    {
        const float sc3 = fmaxf(__uint_as_float(g_scmax[3]), 1e-8f) / 127.f;
        const float sc4 = fmaxf(__uint_as_float(g_scmax[4]), 1e-8f) / 127.f;
        for (int i = tid; i < 10240; i += 256) {       // Wp [o=80][c=128] -> wph [c][80]
            int o = i >> 7, cch = i & 127;
            wph[cch*80 + o] = fq(Wp[i], sc4);
        }
        for (int i = tid; i < 1536; i += 256) {        // Wd [c][9] -> wd [c][12] pad 0
            int cch = i / 12, j = i - cch*12;
            wd[i] = (j < 9) ? fq(Wd[cch*9 + j], sc3) : 0.f;
        }
        if (tid < 80) bph[tid] = bp[tid];
    }

    const int blk = blockIdx.x;              // 768 tiles: 16b x 24y x 2x
    const int b = blk / 48, t = blk % 48;
    const int gy0 = (t >> 1) * 4, gx0 = (t & 1) * 64;
    const int cl = tid >> 5, l  = tid & 31;  // phase A: channel-in-chunk, lane
    const int og = tid >> 6, pg = tid & 63;  // phase B: ch-group, pixel-quad

    const float* cfb = g_cfp + (size_t)b * 128 * PPL;
    uint32_t it_s = (uint32_t)__cvta_generic_to_shared(it);

    auto issue = [&](int ch, int buf) {      // 8 ch x 6 rows x 18 float4 = 864
        const float* srcbase = cfb + (size_t)(ch*8) * PPL + gy0 * PWS + gx0;
        #pragma unroll
        for (int j = 0; j < 4; j++) {
            int idx = tid + j*256;
            if (idx < 864) {
                int c8 = idx / 108, rem = idx % 108;
                int ry = rem / 18,  rx  = rem % 18;
                cp16(it_s + (uint32_t)((buf*ITB + c8*432 + ry*72 + rx*4)*4),
                     srcbase + (size_t)c8*PPL + ry*PWS + rx*4);
            }
        }
        asm volatile("cp.async.commit_group;");
    };

    __syncthreads();                          // weights visible

    unsigned long long acc[40];               // [p=4][q=10] channel pairs
    #pragma unroll
    for (int q = 0; q < 10; q++) {
        unsigned long long bv = pack2(bph[og*20 + 2*q], bph[og*20 + 2*q + 1]);
        acc[q] = bv; acc[10+q] = bv; acc[20+q] = bv; acc[30+q] = bv;
    }

    issue(0, 0);

    for (int ch = 0; ch < 16; ch++) {
        if (ch + 1 < 16) {
            issue(ch + 1, (ch + 1) & 1);
            asm volatile("cp.async.wait_group 1;");
        } else {
            asm volatile("cp.async.wait_group 0;");
        }
        __syncthreads();                      // halo ready; dwb free
        const float* itb = it + (ch & 1) * ITB;

        // ---- phase A: depthwise once per channel ----
        {
            const float4* w4 = (const float4*)(wd + (ch*8 + cl)*12);
            float4 wa = w4[0], wb = w4[1];
            float  w8 = w4[2].x;
            #pragma unroll
            for (int hx = 0; hx < 2; hx++) {
                const int x = l + 32*hx;
                const float* tb = itb + cl*432 + x + 3;
                float d0, d1, d2, d3;
                {
                    float a0 = tb[0],   a1 = tb[1],   a2 = tb[2];
                    d0 = fmaf(a2, wa.z, fmaf(a1, wa.y, a0 * wa.x));
                    a0 = tb[72];  a1 = tb[73];  a2 = tb[74];
                    d0 = fmaf(a0, wa.w, d0); d0 = fmaf(a1, wb.x, d0); d0 = fmaf(a2, wb.y, d0);
                    d1 = fmaf(a2, wa.z, fmaf(a1, wa.y, a0 * wa.x));
                    a0 = tb[144]; a1 = tb[145]; a2 = tb[146];
                    d0 = fmaf(a0, wb.z, d0); d0 = fmaf(a1, wb.w, d0); d0 = fmaf(a2, w8, d0);
                    d1 = fmaf(a0, wa.w, d1); d1 = fmaf(a1, wb.x, d1); d1 = fmaf(a2, wb.y, d1);
                    d2 = fmaf(a2, wa.z, fmaf(a1, wa.y, a0 * wa.x));
                    a0 = tb[216]; a1 = tb[217]; a2 = tb[218];
                    d1 = fmaf(a0, wb.z, d1); d1 = fmaf(a1, wb.w, d1); d1 = fmaf(a2, w8, d1);
                    d2 = fmaf(a0, wa.w, d2); d2 = fmaf(a1, wb.x, d2); d2 = fmaf(a2, wb.y, d2);
                    d3 = fmaf(a2, wa.z, fmaf(a1, wa.y, a0 * wa.x));
                    a0 = tb[288]; a1 = tb[289]; a2 = tb[290];
                    d2 = fmaf(a0, wb.z, d2); d2 = fmaf(a1, wb.w, d2); d2 = fmaf(a2, w8, d2);
                    d3 = fmaf(a0, wa.w, d3); d3 = fmaf(a1, wb.x, d3); d3 = fmaf(a2, wb.y, d3);
                    a0 = tb[360]; a1 = tb[361]; a2 = tb[362];
                    d3 = fmaf(a0, wb.z, d3); d3 = fmaf(a1, wb.w, d3); d3 = fmaf(a2, w8, d3);
                }
                float* dst = dwb + cl*DWS + x;
                dst[0] = d0; dst[64] = d1; dst[128] = d2; dst[192] = d3;
            }
        }
        __syncthreads();                      // dwb visible

        // ---- phase B: 8-k GEMM, b-operand grouped for reuse ----
        #pragma unroll
        for (int kk = 0; kk < 8; kk++) {
            float4 xv = *(const float4*)(dwb + kk*DWS + 4*pg);
            unsigned long long dd0 = pack2(xv.x, xv.x);
            unsigned long long dd1 = pack2(xv.y, xv.y);
            unsigned long long dd2 = pack2(xv.z, xv.z);
            unsigned long long dd3 = pack2(xv.w, xv.w);
            const ulonglong2* wr = (const ulonglong2*)(wph + (ch*8 + kk)*80 + og*20);
            #pragma unroll
            for (int q2 = 0; q2 < 5; q2++) {
                ulonglong2 w = wr[q2];
                ffma2(acc[     2*q2], dd0, w.x);
                ffma2(acc[10 + 2*q2], dd1, w.x);
                ffma2(acc[20 + 2*q2], dd2, w.x);
                ffma2(acc[30 + 2*q2], dd3, w.x);
                ffma2(acc[     2*q2+1], dd0, w.y);
                ffma2(acc[10 + 2*q2+1], dd1, w.y);
                ffma2(acc[20 + 2*q2+1], dd2, w.y);
                ffma2(acc[30 + 2*q2+1], dd3, w.y);
            }
        }
    }

    // epilogue: float4 stores, thread = 4 horizontal px
    const int o0 = og * 20;
    const int y = gy0 + (pg >> 4), x0 = gx0 + ((4*pg) & 63);
    float* ob = out + (size_t)b*82*HWW + y*WW + x0;
    #pragma unroll
    for (int q = 0; q < 10; q++) {
        float2 f0 = unpack2(acc[q]),    f1 = unpack2(acc[10+q]);
        float2 f2 = unpack2(acc[20+q]), f3 = unpack2(acc[30+q]);
        float4 e = make_float4(fmaxf(f0.x,0.f), fmaxf(f1.x,0.f), fmaxf(f2.x,0.f), fmaxf(f3.x,0.f));
        float4 o = make_float4(fmaxf(f0.y,0.f), fmaxf(f1.y,0.f), fmaxf(f2.y,0.f), fmaxf(f3.y,0.f));
        *(float4*)(ob + (size_t)(o0 + 2*q)   * HWW) = e;
        *(float4*)(ob + (size_t)(o0 + 2*q+1) * HWW) = o;
    }
    if (og == 0) {   // flow passthrough ch 80/81
        float4 f0 = *(const float4*)(flow + ((size_t)b*2 + 0)*HWW + y*WW + x0);
        float4 f1 = *(const float4*)(flow + ((size_t)b*2 + 1)*HWW + y*WW + x0);
        *(float4*)(out + ((size_t)b*82 + 80)*HWW + y*WW + x0) = f0;
        *(float4*)(out + ((size_t)b*82 + 81)*HWW + y*WW + x0) = f1;
    }
}

// ---------------- launch ----------------------------------------------------------
extern "C" void kernel_launch(void* const* d_in, const int* in_sizes, int n_in,
                              void* d_out, int out_size) {
    const float* flow = (const float*)d_in[0];
    const float* corr = (const float*)d_in[1];
    const float* Wc1  = (const float*)d_in[2];
    const float* bc1  = (const float*)d_in[3];
    const float* Wf1  = (const float*)d_in[4];
    const float* bf1  = (const float*)d_in[5];
    const float* Wf2  = (const float*)d_in[6];
    const float* bf2  = (const float*)d_in[7];
    const float* Wd   = (const float*)d_in[8];
    const float* Wp   = (const float*)d_in[9];
    const float* bp   = (const float*)d_in[10];
    float* out = (float*)d_out;

    const size_t cor_smem  = (size_t)(CP*48 + 48 + 2*KC*256) * sizeof(float);             // ~65 KB
    const size_t dwpw_smem = (size_t)(10240 + 1536 + 80 + 2*ITB + 8*DWS) * sizeof(float); // ~82 KB
    cudaFuncSetAttribute(corflo_kernel, cudaFuncAttributeMaxDynamicSharedMemorySize, (int)cor_smem);
    cudaFuncSetAttribute(dwpw_kernel,   cudaFuncAttributeMaxDynamicSharedMemorySize, (int)dwpw_smem);

    quant_reduce<<<40, 256>>>(Wc1, Wf1, Wf2, Wd, Wp);
    corflo_kernel<<<1536 + 768, 256, cor_smem>>>(corr, bc1, Wc1, flow, Wf1, bf1, Wf2, bf2);
    dwpw_kernel<<<768, 256, dwpw_smem>>>(flow, Wd, Wp, bp, out);
}

// round 12
// speedup vs baseline: 1.3640x; 1.3640x over previous
#include <cuda_runtime.h>
#include <cstdint>

#define BB 16
#define HH 96
#define WW 128
#define HWW (HH*WW)          // 12288
#define NPIX (BB*HWW)        // 196608
#define CP 196
#define PH 98                // padded rows   (y+1)
#define PWS 136              // padded stride (x+4)
#define PPL (PH*PWS)         // 13328 floats / channel plane

// ---------------- packed-f32x2 helpers -----------------------------------------
__device__ __forceinline__ unsigned long long pack2(float x, float y) {
    unsigned long long r;
    asm("mov.b64 %0, {%1, %2};" : "=l"(r) : "f"(x), "f"(y));
    return r;
}
__device__ __forceinline__ void ffma2(unsigned long long& acc,
                                      unsigned long long a, unsigned long long b) {
    asm("fma.rn.f32x2 %0, %1, %2, %0;" : "+l"(acc) : "l"(a), "l"(b));
}
__device__ __forceinline__ float2 unpack2(unsigned long long v) {
    float2 f;
    asm("mov.b64 {%0, %1}, %2;" : "=f"(f.x), "=f"(f.y) : "l"(v));
    return f;
}
__device__ __forceinline__ void cp16(uint32_t dst, const void* src) {
    asm volatile("cp.async.cg.shared.global [%0], [%1], 16;" :: "r"(dst), "l"(src));
}
__device__ __forceinline__ uint32_t cvt_tf32(float f) {
    uint32_t r;
    asm("cvt.rna.tf32.f32 %0, %1;" : "=r"(r) : "f"(f));
    return r;
}
__device__ __forceinline__ void mma_tf32(float* d, uint32_t a0, uint32_t a1,
                                         uint32_t a2, uint32_t a3,
                                         uint32_t b0, uint32_t b1) {
    asm volatile(
        "mma.sync.aligned.m16n8k8.row.col.f32.tf32.tf32.f32 "
        "{%0,%1,%2,%3}, {%4,%5,%6,%7}, {%8,%9}, {%0,%1,%2,%3};"
        : "+f"(d[0]), "+f"(d[1]), "+f"(d[2]), "+f"(d[3])
        : "r"(a0), "r"(a1), "r"(a2), "r"(a3), "r"(b0), "r"(b1));
}

// ---------------- device scratch ------------------------------------------------
__device__ unsigned g_scmax[5];                   // maxabs bits per tensor
__device__ __align__(16) float g_Wc1m[25*768];    // cor weights: [chunk][ch=96][8 k-interleaved], UNSCALED ints
__device__ __align__(16) float g_Wf1q[64*2];
__device__ __align__(16) float g_Wf2q[64*32];     // [k][32]
__device__ __align__(16) float g_Wdq[128*12];     // [c][12] (9 taps + 3 zero pad)
__device__ __align__(16) float g_Wpq[128*80];     // [c][80]
// padded activations: zero-initialized BSS; borders NEVER written -> stay zero.
__device__ __align__(16) float g_cfp[(size_t)BB*128*PPL];

// ---------------- 1) quantization: init / reduce / pack ---------------------------
__device__ __forceinline__ void qmap(int bid, int& t, int& start, int& cnt) {
    if      (bid < 32)  { t = 0; start = bid * 588;        cnt = 588;  }
    else if (bid == 32) { t = 1; start = 0;                cnt = 128;  }
    else if (bid == 33) { t = 2; start = 0;                cnt = 2048; }
    else if (bid == 34) { t = 3; start = 0;                cnt = 1152; }
    else                { t = 4; start = (bid - 35) * 2048; cnt = 2048; }
}

__global__ void quant_init() { if (threadIdx.x < 5) g_scmax[threadIdx.x] = 0u; }

__global__ void quant_reduce(const float* __restrict__ Wc1,
                             const float* __restrict__ Wf1,
                             const float* __restrict__ Wf2,
                             const float* __restrict__ Wd,
                             const float* __restrict__ Wp) {
    __shared__ float red[256];
    int t, start, cnt;
    qmap(blockIdx.x, t, start, cnt);
    const float* src = (t==0) ? Wc1 : (t==1) ? Wf1 : (t==2) ? Wf2 : (t==3) ? Wd : Wp;

    float m = 0.f;
    for (int i = threadIdx.x; i < cnt; i += 256) m = fmaxf(m, fabsf(src[start + i]));
    red[threadIdx.x] = m;
    __syncthreads();
    for (int s = 128; s > 0; s >>= 1) {
        if (threadIdx.x < s) red[threadIdx.x] = fmaxf(red[threadIdx.x], red[threadIdx.x+s]);
        __syncthreads();
    }
    if (threadIdx.x == 0) atomicMax(&g_scmax[t], __float_as_uint(red[0]));
}

__global__ void quant_pack(const float* __restrict__ Wc1,
                           const float* __restrict__ Wf1,
                           const float* __restrict__ Wf2,
                           const float* __restrict__ Wd,
                           const float* __restrict__ Wp) {
    int t, start, cnt;
    qmap(blockIdx.x, t, start, cnt);
    const float* src = (t==0) ? Wc1 : (t==1) ? Wf1 : (t==2) ? Wf2 : (t==3) ? Wd : Wp;
    const float sc = fmaxf(__uint_as_float(g_scmax[t]), 1e-8f) / 127.f;

    for (int ii = threadIdx.x; ii < cnt; ii += 256) {
        int i = start + ii;
        float qi = rintf(src[i] / sc);
        qi = fminf(fmaxf(qi, -127.f), 127.f);
        float q = qi * sc;
        if (t == 0) {
            // UNSCALED integer, mma B layout: [chunk][ch][j], j = 2*(k%4) + (k%8)/4
            int o = i / CP, k = i % CP;
            int chunk = k >> 3, kk = k & 7;
            int j = 2*(kk & 3) + (kk >> 2);
            g_Wc1m[chunk*768 + o*8 + j] = qi;
        }
        else if (t == 1) g_Wf1q[i] = q;
        else if (t == 2) { int o = i / 64,  k = i % 64; g_Wf2q[k*32 + o] = q; }
        else if (t == 3) { int c = i / 9,   j = i % 9;  g_Wdq[c*12 + j] = q; }
        else             { int o = i / 128, c = i % 128; g_Wpq[c*80 + o] = q; }
    }
}

// ---------------- 2) fused cor (tf32 mma.sync) + flo ------------------------------
// blocks 0..1535 : cor, 128 px (one image row) x 96 ch via m16n8k8 tf32 HMMA.
//                  warp = 16 px x 96 ch, K = 200 (25 chunks of 8, zero-padded W).
// blocks 1536..  : flo, 256 pixels, thread = 1 px x 32 ch.
__global__ __launch_bounds__(256, 2) void corflo_kernel(const float* __restrict__ corr,
                                                        const float* __restrict__ bc1,
                                                        const float* __restrict__ flow,
                                                        const float* __restrict__ bf1,
                                                        const float* __restrict__ bf2) {
    extern __shared__ __align__(16) float sm[];
    const int tid = threadIdx.x;

    if (blockIdx.x >= 1536) {
        // ---------------- flo path (R10 verbatim) ----------------
        float* w1 = sm;            // 128
        float* b1 = sm + 128;      // 64
        float* w2 = sm + 192;      // 2048 [k][32]
        float* b2 = sm + 2240;     // 32
        for (int i = tid; i < 128;  i += 256) w1[i] = g_Wf1q[i];
        for (int i = tid; i < 64;   i += 256) b1[i] = bf1[i];
        for (int i = tid; i < 2048; i += 256) w2[i] = g_Wf2q[i];
        for (int i = tid; i < 32;   i += 256) b2[i] = bf2[i];
        __syncthreads();

        int p  = (blockIdx.x - 1536) * 256 + tid;
        int b  = p / HWW, hw = p % HWW;
        float fx = flow[(size_t)b * 2 * HWW + hw];
        float fy = flow[(size_t)b * 2 * HWW + HWW + hw];

        unsigned long long acc[16];
        #pragma unroll
        for (int q = 0; q < 16; q++) acc[q] = pack2(b2[2*q], b2[2*q+1]);

        #pragma unroll 4
        for (int j = 0; j < 64; j++) {
            float h = fmaxf(fmaf(fx, w1[2*j], fmaf(fy, w1[2*j+1], b1[j])), 0.f);
            unsigned long long hh = pack2(h, h);
            const ulonglong2* wv = reinterpret_cast<const ulonglong2*>(w2 + j*32);
            #pragma unroll
            for (int q = 0; q < 8; q++) {
                ulonglong2 a = wv[q];
                ffma2(acc[2*q],   hh, a.x);
                ffma2(acc[2*q+1], hh, a.y);
            }
        }

        const int y = hw >> 7, x = hw & 127;
        float* obase = g_cfp + ((size_t)(b*128 + 96) * PH + (y+1)) * PWS + x + 4;
        #pragma unroll
        for (int q = 0; q < 16; q++) {
            float2 f = unpack2(acc[q]);
            obase[(size_t)(2*q)   * PPL] = fmaxf(f.x, 0.f);
            obase[(size_t)(2*q+1) * PPL] = fmaxf(f.y, 0.f);
        }
        return;
    }

    // ---------------- cor path: tf32 mma ----------------
    float* bs  = sm;               // 96 bias
    float* Xs  = sm + 96;          // [2][8][128] = 2048
    float* Wsm = sm + 96 + 2048;   // [2][768]    = 1536

    const int blk = blockIdx.x;            // 1536 = 16 b x 96 y
    const int b = blk / 96, y = blk % 96;
    const int w = tid >> 5, lane = tid & 31;
    const int gid = lane >> 2, tig = lane & 3;

    if (tid < 96) bs[tid] = bc1[tid];

    const float* cb = corr + (size_t)b * CP * HWW + (size_t)y * WW;
    uint32_t xs_s = (uint32_t)__cvta_generic_to_shared(Xs);
    uint32_t ws_s = (uint32_t)__cvta_generic_to_shared(Wsm);

    auto issue = [&](int c, int buf) {
        int kk = tid >> 5;                 // 0..7 k-row
        int px4 = (tid & 31) * 4;
        int k = c*8 + kk;
        if (k < CP)
            cp16(xs_s + (uint32_t)((buf*1024 + kk*128 + px4)*4),
                 cb + (size_t)k * HWW + px4);
        if (tid < 192)
            cp16(ws_s + (uint32_t)((buf*768 + tid*4)*4), g_Wc1m + c*768 + tid*4);
        asm volatile("cp.async.commit_group;");
    };

    issue(0, 0);

    float acc[48];                         // 12 ch-tiles x 4
    #pragma unroll
    for (int i = 0; i < 48; i++) acc[i] = 0.f;

    const int pxg = 16*w + gid;

    for (int c = 0; c < 25; c++) {
        if (c + 1 < 25) {
            issue(c + 1, (c + 1) & 1);
            asm volatile("cp.async.wait_group 1;");
        } else {
            asm volatile("cp.async.wait_group 0;");
        }
        __syncthreads();
        const float* xb = Xs  + (c & 1) * 1024;
        const float* wb = Wsm + (c & 1) * 768;

        uint32_t a0 = cvt_tf32(xb[ tig   *128 + pxg    ]);
        uint32_t a1 = cvt_tf32(xb[ tig   *128 + pxg + 8]);
        uint32_t a2 = cvt_tf32(xb[(tig+4)*128 + pxg    ]);
        uint32_t a3 = cvt_tf32(xb[(tig+4)*128 + pxg + 8]);

        #pragma unroll
        for (int t = 0; t < 12; t++) {
            unsigned long long bv =
                *(const unsigned long long*)(wb + (8*t + gid)*8 + 2*tig);
            uint32_t b0 = (uint32_t)bv, b1 = (uint32_t)(bv >> 32);
            mma_tf32(acc + 4*t, a0, a1, a2, a3, b0, b1);
        }
        __syncthreads();                   // buffer consumed before re-issue
    }

    const float sc0 = fmaxf(__uint_as_float(g_scmax[0]), 1e-8f) / 127.f;
    const int x = 16*w + gid;
    #pragma unroll
    for (int t = 0; t < 12; t++) {
        int ch = 8*t + 2*tig;
        float* p0 = g_cfp + ((size_t)(b*128 + ch) * PH + (y+1)) * PWS + 4 + x;
        float* p1 = p0 + (size_t)PPL;      // ch+1 plane
        p0[0] = fmaxf(fmaf(sc0, acc[4*t+0], bs[ch]),   0.f);
        p1[0] = fmaxf(fmaf(sc0, acc[4*t+1], bs[ch+1]), 0.f);
        p0[8] = fmaxf(fmaf(sc0, acc[4*t+2], bs[ch]),   0.f);
        p1[8] = fmaxf(fmaf(sc0, acc[4*t+3], bs[ch+1]), 0.f);
    }
}

// ---------------- 3) fused dw3x3 + pw 128->80 : phase A/B (R10 verbatim) ----------
#define ITB 3456    // floats per halo buffer: 8 ch * 6 rows * 72
#define DWS 260     // dwb channel stride
__global__ __launch_bounds__(256, 2) void dwpw_kernel(const float* __restrict__ flow,
                                                      const float* __restrict__ bp,
                                                      float* __restrict__ out) {
    extern __shared__ __align__(16) float sm2[];
    float* wph = sm2;              // [128][80]  = 10240
    float* wd  = wph + 10240;      // [128][12]  = 1536
    float* bph = wd + 1536;        // 80
    float* it  = bph + 80;         // 2 x [8][6][72] = 6912
    float* dwb = it + 2*ITB;       // [8][260]   = 2080

    const int tid = threadIdx.x;
    for (int i = tid; i < 10240/4; i += 256) ((float4*)wph)[i] = ((const float4*)g_Wpq)[i];
    for (int i = tid; i < 1536/4;  i += 256) ((float4*)wd)[i]  = ((const float4*)g_Wdq)[i];
    if (tid < 80) bph[tid] = bp[tid];

    const int blk = blockIdx.x;              // 768 tiles: 16b x 24y x 2x
    const int b = blk / 48, t = blk % 48;
    const int gy0 = (t >> 1) * 4, gx0 = (t & 1) * 64;
    const int cl = tid >> 5, l  = tid & 31;  // phase A: channel-in-chunk, lane
    const int og = tid >> 6, pg = tid & 63;  // phase B: ch-group, pixel-quad

    const float* cfb = g_cfp + (size_t)b * 128 * PPL;
    uint32_t it_s = (uint32_t)__cvta_generic_to_shared(it);

    auto issue = [&](int ch, int buf) {      // 8 ch x 6 rows x 18 float4 = 864
        const float* srcbase = cfb + (size_t)(ch*8) * PPL + gy0 * PWS + gx0;
        #pragma unroll
        for (int j = 0; j < 4; j++) {
            int idx = tid + j*256;
            if (idx < 864) {
                int c8 = idx / 108, rem = idx % 108;
                int ry = rem / 18,  rx  = rem % 18;
                cp16(it_s + (uint32_t)((buf*ITB + c8*432 + ry*72 + rx*4)*4),
                     srcbase + (size_t)c8*PPL + ry*PWS + rx*4);
            }
        }
        asm volatile("cp.async.commit_group;");
    };

    __syncthreads();                          // weights visible

    unsigned long long acc[40];               // [p=4][q=10] channel pairs
    #pragma unroll
    for (int q = 0; q < 10; q++) {
        unsigned long long bv = pack2(bph[og*20 + 2*q], bph[og*20 + 2*q + 1]);
        acc[q] = bv; acc[10+q] = bv; acc[20+q] = bv; acc[30+q] = bv;
    }

    issue(0, 0);

    for (int ch = 0; ch < 16; ch++) {
        if (ch + 1 < 16) {
            issue(ch + 1, (ch + 1) & 1);
            asm volatile("cp.async.wait_group 1;");
        } else {
            asm volatile("cp.async.wait_group 0;");
        }
        __syncthreads();                      // halo ready; dwb free
        const float* itb = it + (ch & 1) * ITB;

        // ---- phase A: depthwise once per channel ----
        {
            const float4* w4 = (const float4*)(wd + (ch*8 + cl)*12);
            float4 wa = w4[0], wb = w4[1];
            float  w8 = w4[2].x;
            #pragma unroll
            for (int hx = 0; hx < 2; hx++) {
                const int x = l + 32*hx;
                const float* tb = itb + cl*432 + x + 3;
                float d0, d1, d2, d3;
                {
                    float a0 = tb[0],   a1 = tb[1],   a2 = tb[2];
                    d0 = fmaf(a2, wa.z, fmaf(a1, wa.y, a0 * wa.x));
                    a0 = tb[72];  a1 = tb[73];  a2 = tb[74];
                    d0 = fmaf(a0, wa.w, d0); d0 = fmaf(a1, wb.x, d0); d0 = fmaf(a2, wb.y, d0);
                    d1 = fmaf(a2, wa.z, fmaf(a1, wa.y, a0 * wa.x));
                    a0 = tb[144]; a1 = tb[145]; a2 = tb[146];
                    d0 = fmaf(a0, wb.z, d0); d0 = fmaf(a1, wb.w, d0); d0 = fmaf(a2, w8, d0);
                    d1 = fmaf(a0, wa.w, d1); d1 = fmaf(a1, wb.x, d1); d1 = fmaf(a2, wb.y, d1);
                    d2 = fmaf(a2, wa.z, fmaf(a1, wa.y, a0 * wa.x));
                    a0 = tb[216]; a1 = tb[217]; a2 = tb[218];
                    d1 = fmaf(a0, wb.z, d1); d1 = fmaf(a1, wb.w, d1); d1 = fmaf(a2, w8, d1);
                    d2 = fmaf(a0, wa.w, d2); d2 = fmaf(a1, wb.x, d2); d2 = fmaf(a2, wb.y, d2);
                    d3 = fmaf(a2, wa.z, fmaf(a1, wa.y, a0 * wa.x));
                    a0 = tb[288]; a1 = tb[289]; a2 = tb[290];
                    d2 = fmaf(a0, wb.z, d2); d2 = fmaf(a1, wb.w, d2); d2 = fmaf(a2, w8, d2);
                    d3 = fmaf(a0, wa.w, d3); d3 = fmaf(a1, wb.x, d3); d3 = fmaf(a2, wb.y, d3);
                    a0 = tb[360]; a1 = tb[361]; a2 = tb[362];
                    d3 = fmaf(a0, wb.z, d3); d3 = fmaf(a1, wb.w, d3); d3 = fmaf(a2, w8, d3);
                }
                float* dst = dwb + cl*DWS + x;
                dst[0] = d0; dst[64] = d1; dst[128] = d2; dst[192] = d3;
            }
        }
        __syncthreads();                      // dwb visible

        // ---- phase B: 8-k GEMM (R10 emission order) ----
        #pragma unroll
        for (int kk = 0; kk < 8; kk++) {
            float4 xv = *(const float4*)(dwb + kk*DWS + 4*pg);
            unsigned long long dd0 = pack2(xv.x, xv.x);
            unsigned long long dd1 = pack2(xv.y, xv.y);
            unsigned long long dd2 = pack2(xv.z, xv.z);
            unsigned long long dd3 = pack2(xv.w, xv.w);
            const ulonglong2* wr = (const ulonglong2*)(wph + (ch*8 + kk)*80 + og*20);
            #pragma unroll
            for (int q2 = 0; q2 < 5; q2++) {
                ulonglong2 w = wr[q2];
                ffma2(acc[     2*q2], dd0, w.x); ffma2(acc[     2*q2+1], dd0, w.y);
                ffma2(acc[10 + 2*q2], dd1, w.x); ffma2(acc[10 + 2*q2+1], dd1, w.y);
                ffma2(acc[20 + 2*q2], dd2, w.x); ffma2(acc[20 + 2*q2+1], dd2, w.y);
                ffma2(acc[30 + 2*q2], dd3, w.x); ffma2(acc[30 + 2*q2+1], dd3, w.y);
            }
        }
    }

    // epilogue: float4 stores, thread = 4 horizontal px
    const int o0 = og * 20;
    const int y = gy0 + (pg >> 4), x0 = gx0 + ((4*pg) & 63);
    float* ob = out + (size_t)b*82*HWW + y*WW + x0;
    #pragma unroll
    for (int q = 0; q < 10; q++) {
        float2 f0 = unpack2(acc[q]),    f1 = unpack2(acc[10+q]);
        float2 f2 = unpack2(acc[20+q]), f3 = unpack2(acc[30+q]);
        float4 e = make_float4(fmaxf(f0.x,0.f), fmaxf(f1.x,0.f), fmaxf(f2.x,0.f), fmaxf(f3.x,0.f));
        float4 o = make_float4(fmaxf(f0.y,0.f), fmaxf(f1.y,0.f), fmaxf(f2.y,0.f), fmaxf(f3.y,0.f));
        *(float4*)(ob + (size_t)(o0 + 2*q)   * HWW) = e;
        *(float4*)(ob + (size_t)(o0 + 2*q+1) * HWW) = o;
    }
    if (og == 0) {   // flow passthrough ch 80/81
        float4 f0 = *(const float4*)(flow + ((size_t)b*2 + 0)*HWW + y*WW + x0);
        float4 f1 = *(const float4*)(flow + ((size_t)b*2 + 1)*HWW + y*WW + x0);
        *(float4*)(out + ((size_t)b*82 + 80)*HWW + y*WW + x0) = f0;
        *(float4*)(out + ((size_t)b*82 + 81)*HWW + y*WW + x0) = f1;
    }
}

// ---------------- launch ----------------------------------------------------------
extern "C" void kernel_launch(void* const* d_in, const int* in_sizes, int n_in,
                              void* d_out, int out_size) {
    const float* flow = (const float*)d_in[0];
    const float* corr = (const float*)d_in[1];
    const float* Wc1  = (const float*)d_in[2];
    const float* bc1  = (const float*)d_in[3];
    const float* Wf1  = (const float*)d_in[4];
    const float* bf1  = (const float*)d_in[5];
    const float* Wf2  = (const float*)d_in[6];
    const float* bf2  = (const float*)d_in[7];
    const float* Wd   = (const float*)d_in[8];
    const float* Wp   = (const float*)d_in[9];
    const float* bp   = (const float*)d_in[10];
    float* out = (float*)d_out;

    const size_t cor_smem  = (size_t)(96 + 2048 + 1536) * sizeof(float);              // ~14.4 KB
    const size_t dwpw_smem = (size_t)(10240 + 1536 + 80 + 2*ITB + 8*DWS) * sizeof(float); // ~82 KB
    cudaFuncSetAttribute(corflo_kernel, cudaFuncAttributeMaxDynamicSharedMemorySize, (int)cor_smem);
    cudaFuncSetAttribute(dwpw_kernel,   cudaFuncAttributeMaxDynamicSharedMemorySize, (int)dwpw_smem);

    quant_init<<<1, 32>>>();
    quant_reduce<<<40, 256>>>(Wc1, Wf1, Wf2, Wd, Wp);
    quant_pack<<<40, 256>>>(Wc1, Wf1, Wf2, Wd, Wp);
    corflo_kernel<<<1536 + 768, 256, cor_smem>>>(corr, bc1, flow, bf1, bf2);
    dwpw_kernel<<<768, 256, dwpw_smem>>>(flow, bp, out);
}

// round 13
// speedup vs baseline: 1.4834x; 1.0876x over previous
#include <cuda_runtime.h>
#include <cstdint>

#define BB 16
#define HH 96
#define WW 128
#define HWW (HH*WW)          // 12288
#define NPIX (BB*HWW)        // 196608
#define CP 196
#define PH 98                // padded rows   (y+1)
#define PWS 136              // padded stride (x+4)
#define PPL (PH*PWS)         // 13328 floats / channel plane

#define XROW 136             // Xs row stride (8 mod 32 -> conflict-free A frags)
#define NCHK16 13            // K chunks of 16 (pad to 208)

// ---------------- packed-f32x2 helpers -----------------------------------------
__device__ __forceinline__ unsigned long long pack2(float x, float y) {
    unsigned long long r;
    asm("mov.b64 %0, {%1, %2};" : "=l"(r) : "f"(x), "f"(y));
    return r;
}
__device__ __forceinline__ void ffma2(unsigned long long& acc,
                                      unsigned long long a, unsigned long long b) {
    asm("fma.rn.f32x2 %0, %1, %2, %0;" : "+l"(acc) : "l"(a), "l"(b));
}
__device__ __forceinline__ float2 unpack2(unsigned long long v) {
    float2 f;
    asm("mov.b64 {%0, %1}, %2;" : "=f"(f.x), "=f"(f.y) : "l"(v));
    return f;
}
__device__ __forceinline__ void cp16(uint32_t dst, const void* src) {
    asm volatile("cp.async.cg.shared.global [%0], [%1], 16;" :: "r"(dst), "l"(src));
}
__device__ __forceinline__ uint32_t cvt_tf32(float f) {
    uint32_t r;
    asm("cvt.rna.tf32.f32 %0, %1;" : "=r"(r) : "f"(f));
    return r;
}
__device__ __forceinline__ void mma_tf32(float* d, uint32_t a0, uint32_t a1,
                                         uint32_t a2, uint32_t a3,
                                         uint32_t b0, uint32_t b1) {
    asm volatile(
        "mma.sync.aligned.m16n8k8.row.col.f32.tf32.tf32.f32 "
        "{%0,%1,%2,%3}, {%4,%5,%6,%7}, {%8,%9}, {%0,%1,%2,%3};"
        : "+f"(d[0]), "+f"(d[1]), "+f"(d[2]), "+f"(d[3])
        : "r"(a0), "r"(a1), "r"(a2), "r"(a3), "r"(b0), "r"(b1));
}

// ---------------- device scratch ------------------------------------------------
__device__ unsigned g_scmax[5];                   // maxabs bits (BSS=0; atomicMax idempotent)
__device__ __align__(16) float g_Wc1m[NCHK16*1536]; // cor W: [chunk16][sub2][96][8], UNSCALED ints, zero-pad
__device__ __align__(16) float g_Wf1q[64*2];
__device__ __align__(16) float g_Wf2q[64*32];     // [k][32]
__device__ __align__(16) float g_Wdq[128*12];     // [c][12] (9 taps + 3 zero pad)
__device__ __align__(16) float g_Wpq[128*80];     // [c][80]
// padded activations: zero-initialized BSS; borders NEVER written -> stay zero.
__device__ __align__(16) float g_cfp[(size_t)BB*128*PPL];

// ---------------- 1) quantization: reduce / pack ---------------------------------
__device__ __forceinline__ void qmap(int bid, int& t, int& start, int& cnt) {
    if      (bid < 32)  { t = 0; start = bid * 588;        cnt = 588;  }
    else if (bid == 32) { t = 1; start = 0;                cnt = 128;  }
    else if (bid == 33) { t = 2; start = 0;                cnt = 2048; }
    else if (bid == 34) { t = 3; start = 0;                cnt = 1152; }
    else                { t = 4; start = (bid - 35) * 2048; cnt = 2048; }
}

__global__ void quant_reduce(const float* __restrict__ Wc1,
                             const float* __restrict__ Wf1,
                             const float* __restrict__ Wf2,
                             const float* __restrict__ Wd,
                             const float* __restrict__ Wp) {
    __shared__ float red[256];
    int t, start, cnt;
    qmap(blockIdx.x, t, start, cnt);
    const float* src = (t==0) ? Wc1 : (t==1) ? Wf1 : (t==2) ? Wf2 : (t==3) ? Wd : Wp;

    float m = 0.f;
    for (int i = threadIdx.x; i < cnt; i += 256) m = fmaxf(m, fabsf(src[start + i]));
    red[threadIdx.x] = m;
    __syncthreads();
    for (int s = 128; s > 0; s >>= 1) {
        if (threadIdx.x < s) red[threadIdx.x] = fmaxf(red[threadIdx.x], red[threadIdx.x+s]);
        __syncthreads();
    }
    if (threadIdx.x == 0) atomicMax(&g_scmax[t], __float_as_uint(red[0]));
}

__global__ void quant_pack(const float* __restrict__ Wc1,
                           const float* __restrict__ Wf1,
                           const float* __restrict__ Wf2,
                           const float* __restrict__ Wd,
                           const float* __restrict__ Wp) {
    int t, start, cnt;
    qmap(blockIdx.x, t, start, cnt);
    const float* src = (t==0) ? Wc1 : (t==1) ? Wf1 : (t==2) ? Wf2 : (t==3) ? Wd : Wp;
    const float sc = fmaxf(__uint_as_float(g_scmax[t]), 1e-8f) / 127.f;

    for (int ii = threadIdx.x; ii < cnt; ii += 256) {
        int i = start + ii;
        float qi = rintf(src[i] / sc);
        qi = fminf(fmaxf(qi, -127.f), 127.f);
        float q = qi * sc;
        if (t == 0) {
            // UNSCALED integer; mma B layout: [chunk16][sub][ch][j], j = 2*(k%4) + (k%8)/4
            int o = i / CP, k = i % CP;
            int chunk = k >> 4, sub = (k >> 3) & 1, kk = k & 7;
            int j = 2*(kk & 3) + (kk >> 2);
            g_Wc1m[chunk*1536 + sub*768 + o*8 + j] = qi;
        }
        else if (t == 1) g_Wf1q[i] = q;
        else if (t == 2) { int o = i / 64,  k = i % 64; g_Wf2q[k*32 + o] = q; }
        else if (t == 3) { int c = i / 9,   j = i % 9;  g_Wdq[c*12 + j] = q; }
        else             { int o = i / 128, c = i % 128; g_Wpq[c*80 + o] = q; }
    }
}

// ---------------- 2) fused cor (tf32 mma.sync) + flo ------------------------------
// blocks 0..1535 : cor, 128 px (one image row) x 96 ch via m16n8k8 tf32 HMMA.
//                  warp = 16 px x 96 ch; K chunks of 16 (13 chunks, zero-pad W).
// blocks 1536..  : flo, 256 pixels, thread = 1 px x 32 ch.
__global__ __launch_bounds__(256, 2) void corflo_kernel(const float* __restrict__ corr,
                                                        const float* __restrict__ bc1,
                                                        const float* __restrict__ flow,
                                                        const float* __restrict__ bf1,
                                                        const float* __restrict__ bf2) {
    extern __shared__ __align__(16) float sm[];
    const int tid = threadIdx.x;

    if (blockIdx.x >= 1536) {
        // ---------------- flo path ----------------
        float* w1 = sm;            // 128
        float* b1 = sm + 128;      // 64
        float* w2 = sm + 192;      // 2048 [k][32]
        float* b2 = sm + 2240;     // 32
        for (int i = tid; i < 128;  i += 256) w1[i] = g_Wf1q[i];
        for (int i = tid; i < 64;   i += 256) b1[i] = bf1[i];
        for (int i = tid; i < 2048; i += 256) w2[i] = g_Wf2q[i];
        for (int i = tid; i < 32;   i += 256) b2[i] = bf2[i];
        __syncthreads();

        int p  = (blockIdx.x - 1536) * 256 + tid;
        int b  = p / HWW, hw = p % HWW;
        float fx = flow[(size_t)b * 2 * HWW + hw];
        float fy = flow[(size_t)b * 2 * HWW + HWW + hw];

        unsigned long long acc[16];
        #pragma unroll
        for (int q = 0; q < 16; q++) acc[q] = pack2(b2[2*q], b2[2*q+1]);

        #pragma unroll 4
        for (int j = 0; j < 64; j++) {
            float h = fmaxf(fmaf(fx, w1[2*j], fmaf(fy, w1[2*j+1], b1[j])), 0.f);
            unsigned long long hh = pack2(h, h);
            const ulonglong2* wv = reinterpret_cast<const ulonglong2*>(w2 + j*32);
            #pragma unroll
            for (int q = 0; q < 8; q++) {
                ulonglong2 a = wv[q];
                ffma2(acc[2*q],   hh, a.x);
                ffma2(acc[2*q+1], hh, a.y);
            }
        }

        const int y = hw >> 7, x = hw & 127;
        float* obase = g_cfp + ((size_t)(b*128 + 96) * PH + (y+1)) * PWS + x + 4;
        #pragma unroll
        for (int q = 0; q < 16; q++) {
            float2 f = unpack2(acc[q]);
            obase[(size_t)(2*q)   * PPL] = fmaxf(f.x, 0.f);
            obase[(size_t)(2*q+1) * PPL] = fmaxf(f.y, 0.f);
        }
        return;
    }

    // ---------------- cor path: tf32 mma, 16-k chunks ----------------
    float* bs  = sm;               // 96 bias
    float* Xs  = sm + 96;          // [2][16][136] = 4352
    float* Wsm = sm + 96 + 4352;   // [2][1536]    = 3072

    const int blk = blockIdx.x;            // 1536 = 16 b x 96 y
    const int b = blk / 96, y = blk % 96;
    const int w = tid >> 5, lane = tid & 31;
    const int gid = lane >> 2, tig = lane & 3;

    if (tid < 96) bs[tid] = bc1[tid];

    const float* cb = corr + (size_t)b * CP * HWW + (size_t)y * WW;
    uint32_t xs_s = (uint32_t)__cvta_generic_to_shared(Xs);
    uint32_t ws_s = (uint32_t)__cvta_generic_to_shared(Wsm);

    auto issue = [&](int c, int buf) {
        #pragma unroll
        for (int j = 0; j < 2; j++) {      // 16 rows x 32 float4 = 512
            int idx = tid + j*256;
            int row = idx >> 5, c4 = idx & 31;
            int k = c*16 + row;
            if (k < CP)
                cp16(xs_s + (uint32_t)((buf*(16*XROW) + row*XROW + c4*4)*4),
                     cb + (size_t)k * HWW + c4*4);
        }
        #pragma unroll
        for (int j = 0; j < 2; j++) {      // 1536 floats = 384 float4
            int idx = tid + j*256;
            if (idx < 384)
                cp16(ws_s + (uint32_t)((buf*1536 + idx*4)*4), g_Wc1m + c*1536 + idx*4);
        }
        asm volatile("cp.async.commit_group;");
    };

    issue(0, 0);

    float acc[48];                         // 12 ch-tiles x 4
    #pragma unroll
    for (int i = 0; i < 48; i++) acc[i] = 0.f;

    const int pxg = 16*w + gid;

    for (int c = 0; c < NCHK16; c++) {
        if (c + 1 < NCHK16) {
            issue(c + 1, (c + 1) & 1);
            asm volatile("cp.async.wait_group 1;");
        } else {
            asm volatile("cp.async.wait_group 0;");
        }
        __syncthreads();
        const float* xb = Xs  + (c & 1) * (16*XROW);
        const float* wb = Wsm + (c & 1) * 1536;

        #pragma unroll
        for (int s = 0; s < 2; s++) {
            uint32_t a0 = cvt_tf32(xb[(s*8 + tig    )*XROW + pxg    ]);
            uint32_t a1 = cvt_tf32(xb[(s*8 + tig    )*XROW + pxg + 8]);
            uint32_t a2 = cvt_tf32(xb[(s*8 + tig + 4)*XROW + pxg    ]);
            uint32_t a3 = cvt_tf32(xb[(s*8 + tig + 4)*XROW + pxg + 8]);
            const float* wsb = wb + s*768;
            #pragma unroll
            for (int t = 0; t < 12; t++) {
                unsigned long long bv =
                    *(const unsigned long long*)(wsb + (8*t + gid)*8 + 2*tig);
                uint32_t b0 = (uint32_t)bv, b1 = (uint32_t)(bv >> 32);
                mma_tf32(acc + 4*t, a0, a1, a2, a3, b0, b1);
            }
        }
        __syncthreads();                   // buffer consumed before re-issue
    }

    const float sc0 = fmaxf(__uint_as_float(g_scmax[0]), 1e-8f) / 127.f;
    const int x = 16*w + gid;
    #pragma unroll
    for (int t = 0; t < 12; t++) {
        int ch = 8*t + 2*tig;
        float* p0 = g_cfp + ((size_t)(b*128 + ch) * PH + (y+1)) * PWS + 4 + x;
        float* p1 = p0 + (size_t)PPL;      // ch+1 plane
        p0[0] = fmaxf(fmaf(sc0, acc[4*t+0], bs[ch]),   0.f);
        p1[0] = fmaxf(fmaf(sc0, acc[4*t+1], bs[ch+1]), 0.f);
        p0[8] = fmaxf(fmaf(sc0, acc[4*t+2], bs[ch]),   0.f);
        p1[8] = fmaxf(fmaf(sc0, acc[4*t+3], bs[ch+1]), 0.f);
    }
}

// ---------------- 3) fused dw3x3 + pw 128->80 : phase A/B -------------------------
#define ITB 3456    // floats per halo buffer: 8 ch * 6 rows * 72
#define DWS 260     // dwb channel stride
__global__ __launch_bounds__(256, 2) void dwpw_kernel(const float* __restrict__ flow,
                                                      const float* __restrict__ bp,
                                                      float* __restrict__ out) {
    extern __shared__ __align__(16) float sm2[];
    float* wph = sm2;              // [128][80]  = 10240
    float* wd  = wph + 10240;      // [128][12]  = 1536
    float* bph = wd + 1536;        // 80
    float* it  = bph + 80;         // 2 x [8][6][72] = 6912
    float* dwb = it + 2*ITB;       // [8][260]   = 2080

    const int tid = threadIdx.x;
    for (int i = tid; i < 10240/4; i += 256) ((float4*)wph)[i] = ((const float4*)g_Wpq)[i];
    for (int i = tid; i < 1536/4;  i += 256) ((float4*)wd)[i]  = ((const float4*)g_Wdq)[i];
    if (tid < 80) bph[tid] = bp[tid];

    const int blk = blockIdx.x;              // 768 tiles: 16b x 24y x 2x
    const int b = blk / 48, t = blk % 48;
    const int gy0 = (t >> 1) * 4, gx0 = (t & 1) * 64;
    const int cl = tid >> 5, l  = tid & 31;  // phase A: channel-in-chunk, lane
    const int og = tid >> 6, pg = tid & 63;  // phase B: ch-group, pixel-quad

    const float* cfb = g_cfp + (size_t)b * 128 * PPL;
    uint32_t it_s = (uint32_t)__cvta_generic_to_shared(it);

    auto issue = [&](int ch, int buf) {      // 8 ch x 6 rows x 18 float4 = 864
        const float* srcbase = cfb + (size_t)(ch*8) * PPL + gy0 * PWS + gx0;
        #pragma unroll
        for (int j = 0; j < 4; j++) {
            int idx = tid + j*256;
            if (idx < 864) {
                int c8 = idx / 108, rem = idx % 108;
                int ry = rem / 18,  rx  = rem % 18;
                cp16(it_s + (uint32_t)((buf*ITB + c8*432 + ry*72 + rx*4)*4),
                     srcbase + (size_t)c8*PPL + ry*PWS + rx*4);
            }
        }
        asm volatile("cp.async.commit_group;");
    };

    __syncthreads();                          // weights visible

    unsigned long long acc[40];               // [p=4][q=10] channel pairs
    #pragma unroll
    for (int q = 0; q < 10; q++) {
        unsigned long long bv = pack2(bph[og*20 + 2*q], bph[og*20 + 2*q + 1]);
        acc[q] = bv; acc[10+q] = bv; acc[20+q] = bv; acc[30+q] = bv;
    }

    issue(0, 0);

    for (int ch = 0; ch < 16; ch++) {
        if (ch + 1 < 16) {
            issue(ch + 1, (ch + 1) & 1);
            asm volatile("cp.async.wait_group 1;");
        } else {
            asm volatile("cp.async.wait_group 0;");
        }
        __syncthreads();                      // halo ready; dwb free
        const float* itb = it + (ch & 1) * ITB;

        // ---- phase A: depthwise once per channel ----
        {
            const float4* w4 = (const float4*)(wd + (ch*8 + cl)*12);
            float4 wa = w4[0], wb = w4[1];
            float  w8 = w4[2].x;
            #pragma unroll
            for (int hx = 0; hx < 2; hx++) {
                const int x = l + 32*hx;
                const float* tb = itb + cl*432 + x + 3;
                float d0, d1, d2, d3;
                {
                    float a0 = tb[0],   a1 = tb[1],   a2 = tb[2];
                    d0 = fmaf(a2, wa.z, fmaf(a1, wa.y, a0 * wa.x));
                    a0 = tb[72];  a1 = tb[73];  a2 = tb[74];
                    d0 = fmaf(a0, wa.w, d0); d0 = fmaf(a1, wb.x, d0); d0 = fmaf(a2, wb.y, d0);
                    d1 = fmaf(a2, wa.z, fmaf(a1, wa.y, a0 * wa.x));
                    a0 = tb[144]; a1 = tb[145]; a2 = tb[146];
                    d0 = fmaf(a0, wb.z, d0); d0 = fmaf(a1, wb.w, d0); d0 = fmaf(a2, w8, d0);
                    d1 = fmaf(a0, wa.w, d1); d1 = fmaf(a1, wb.x, d1); d1 = fmaf(a2, wb.y, d1);
                    d2 = fmaf(a2, wa.z, fmaf(a1, wa.y, a0 * wa.x));
                    a0 = tb[216]; a1 = tb[217]; a2 = tb[218];
                    d1 = fmaf(a0, wb.z, d1); d1 = fmaf(a1, wb.w, d1); d1 = fmaf(a2, w8, d1);
                    d2 = fmaf(a0, wa.w, d2); d2 = fmaf(a1, wb.x, d2); d2 = fmaf(a2, wb.y, d2);
                    d3 = fmaf(a2, wa.z, fmaf(a1, wa.y, a0 * wa.x));
                    a0 = tb[288]; a1 = tb[289]; a2 = tb[290];
                    d2 = fmaf(a0, wb.z, d2); d2 = fmaf(a1, wb.w, d2); d2 = fmaf(a2, w8, d2);
                    d3 = fmaf(a0, wa.w, d3); d3 = fmaf(a1, wb.x, d3); d3 = fmaf(a2, wb.y, d3);
                    a0 = tb[360]; a1 = tb[361]; a2 = tb[362];
                    d3 = fmaf(a0, wb.z, d3); d3 = fmaf(a1, wb.w, d3); d3 = fmaf(a2, w8, d3);
                }
                float* dst = dwb + cl*DWS + x;
                dst[0] = d0; dst[64] = d1; dst[128] = d2; dst[192] = d3;
            }
        }
        __syncthreads();                      // dwb visible

        // ---- phase B: 8-k GEMM ----
        #pragma unroll
        for (int kk = 0; kk < 8; kk++) {
            float4 xv = *(const float4*)(dwb + kk*DWS + 4*pg);
            unsigned long long dd0 = pack2(xv.x, xv.x);
            unsigned long long dd1 = pack2(xv.y, xv.y);
            unsigned long long dd2 = pack2(xv.z, xv.z);
            unsigned long long dd3 = pack2(xv.w, xv.w);
            const ulonglong2* wr = (const ulonglong2*)(wph + (ch*8 + kk)*80 + og*20);
            #pragma unroll
            for (int q2 = 0; q2 < 5; q2++) {
                ulonglong2 w = wr[q2];
                ffma2(acc[     2*q2], dd0, w.x); ffma2(acc[     2*q2+1], dd0, w.y);
                ffma2(acc[10 + 2*q2], dd1, w.x); ffma2(acc[10 + 2*q2+1], dd1, w.y);
                ffma2(acc[20 + 2*q2], dd2, w.x); ffma2(acc[20 + 2*q2+1], dd2, w.y);
                ffma2(acc[30 + 2*q2], dd3, w.x); ffma2(acc[30 + 2*q2+1], dd3, w.y);
            }
        }
    }

    // epilogue: float4 stores, thread = 4 horizontal px
    const int o0 = og * 20;
    const int y = gy0 + (pg >> 4), x0 = gx0 + ((4*pg) & 63);
    float* ob = out + (size_t)b*82*HWW + y*WW + x0;
    #pragma unroll
    for (int q = 0; q < 10; q++) {
        float2 f0 = unpack2(acc[q]),    f1 = unpack2(acc[10+q]);
        float2 f2 = unpack2(acc[20+q]), f3 = unpack2(acc[30+q]);
        float4 e = make_float4(fmaxf(f0.x,0.f), fmaxf(f1.x,0.f), fmaxf(f2.x,0.f), fmaxf(f3.x,0.f));
        float4 o = make_float4(fmaxf(f0.y,0.f), fmaxf(f1.y,0.f), fmaxf(f2.y,0.f), fmaxf(f3.y,0.f));
        *(float4*)(ob + (size_t)(o0 + 2*q)   * HWW) = e;
        *(float4*)(ob + (size_t)(o0 + 2*q+1) * HWW) = o;
    }
    if (og == 0) {   // flow passthrough ch 80/81
        float4 f0 = *(const float4*)(flow + ((size_t)b*2 + 0)*HWW + y*WW + x0);
        float4 f1 = *(const float4*)(flow + ((size_t)b*2 + 1)*HWW + y*WW + x0);
        *(float4*)(out + ((size_t)b*82 + 80)*HWW + y*WW + x0) = f0;
        *(float4*)(out + ((size_t)b*82 + 81)*HWW + y*WW + x0) = f1;
    }
}

// ---------------- launch ----------------------------------------------------------
extern "C" void kernel_launch(void* const* d_in, const int* in_sizes, int n_in,
                              void* d_out, int out_size) {
    const float* flow = (const float*)d_in[0];
    const float* corr = (const float*)d_in[1];
    const float* Wc1  = (const float*)d_in[2];
    const float* bc1  = (const float*)d_in[3];
    const float* Wf1  = (const float*)d_in[4];
    const float* bf1  = (const float*)d_in[5];
    const float* Wf2  = (const float*)d_in[6];
    const float* bf2  = (const float*)d_in[7];
    const float* Wd   = (const float*)d_in[8];
    const float* Wp   = (const float*)d_in[9];
    const float* bp   = (const float*)d_in[10];
    float* out = (float*)d_out;

    const size_t cor_smem  = (size_t)(96 + 2*16*XROW + 2*1536) * sizeof(float);           // ~30 KB
    const size_t dwpw_smem = (size_t)(10240 + 1536 + 80 + 2*ITB + 8*DWS) * sizeof(float); // ~82 KB
    cudaFuncSetAttribute(corflo_kernel, cudaFuncAttributeMaxDynamicSharedMemorySize, (int)cor_smem);
    cudaFuncSetAttribute(dwpw_kernel,   cudaFuncAttributeMaxDynamicSharedMemorySize, (int)dwpw_smem);

    quant_reduce<<<40, 256>>>(Wc1, Wf1, Wf2, Wd, Wp);
    quant_pack<<<40, 256>>>(Wc1, Wf1, Wf2, Wd, Wp);
    corflo_kernel<<<1536 + 768, 256, cor_smem>>>(corr, bc1, flow, bf1, bf2);
    dwpw_kernel<<<768, 256, dwpw_smem>>>(flow, bp, out);
}

// round 14
// speedup vs baseline: 1.8767x; 1.2651x over previous
#include <cuda_runtime.h>
#include <cstdint>

#define BB 16
#define HH 96
#define WW 128
#define HWW (HH*WW)          // 12288
#define NPIX (BB*HWW)        // 196608
#define CP 196
#define PH 98                // padded rows   (y+1)
#define PWS 136              // padded stride (x+4)
#define PPL (PH*PWS)         // 13328 floats / channel plane

#define XROW 136             // Xs row stride (8 mod 32 -> conflict-free A frags)
#define NCHK16 13            // K chunks of 16 (pad to 208)

// ---------------- packed-f32x2 helpers -----------------------------------------
__device__ __forceinline__ unsigned long long pack2(float x, float y) {
    unsigned long long r;
    asm("mov.b64 %0, {%1, %2};" : "=l"(r) : "f"(x), "f"(y));
    return r;
}
__device__ __forceinline__ void ffma2(unsigned long long& acc,
                                      unsigned long long a, unsigned long long b) {
    asm("fma.rn.f32x2 %0, %1, %2, %0;" : "+l"(acc) : "l"(a), "l"(b));
}
__device__ __forceinline__ float2 unpack2(unsigned long long v) {
    float2 f;
    asm("mov.b64 {%0, %1}, %2;" : "=f"(f.x), "=f"(f.y) : "l"(v));
    return f;
}
__device__ __forceinline__ void cp16(uint32_t dst, const void* src) {
    asm volatile("cp.async.cg.shared.global [%0], [%1], 16;" :: "r"(dst), "l"(src));
}
__device__ __forceinline__ uint32_t cvt_tf32(float f) {
    uint32_t r;
    asm("cvt.rna.tf32.f32 %0, %1;" : "=r"(r) : "f"(f));
    return r;
}
__device__ __forceinline__ void mma_tf32(float* d, uint32_t a0, uint32_t a1,
                                         uint32_t a2, uint32_t a3,
                                         uint32_t b0, uint32_t b1) {
    asm volatile(
        "mma.sync.aligned.m16n8k8.row.col.f32.tf32.tf32.f32 "
        "{%0,%1,%2,%3}, {%4,%5,%6,%7}, {%8,%9}, {%0,%1,%2,%3};"
        : "+f"(d[0]), "+f"(d[1]), "+f"(d[2]), "+f"(d[3])
        : "r"(a0), "r"(a1), "r"(a2), "r"(a3), "r"(b0), "r"(b1));
}

// ---------------- device scratch ------------------------------------------------
__device__ unsigned g_scmax[5];                   // maxabs bits (BSS=0; atomicMax idempotent)
__device__ __align__(16) float g_Wc1m[NCHK16*1536]; // cor W: [chunk16][sub2][96][8], UNSCALED ints, zero-pad
__device__ __align__(16) float g_Wf1q[64*2];
__device__ __align__(16) float g_Wf2q[64*32];     // [k][32]
__device__ __align__(16) float g_Wdq[128*12];     // [c][12] (9 taps + 3 zero pad)
__device__ __align__(16) float g_Wpm[16*640];     // pw W: [chunk8][80][8] mma-interleave, UNSCALED ints
// padded activations: zero-initialized BSS; borders NEVER written -> stay zero.
__device__ __align__(16) float g_cfp[(size_t)BB*128*PPL];

// ---------------- 1) quantization: reduce / pack ---------------------------------
__device__ __forceinline__ void qmap(int bid, int& t, int& start, int& cnt) {
    if      (bid < 32)  { t = 0; start = bid * 588;        cnt = 588;  }
    else if (bid == 32) { t = 1; start = 0;                cnt = 128;  }
    else if (bid == 33) { t = 2; start = 0;                cnt = 2048; }
    else if (bid == 34) { t = 3; start = 0;                cnt = 1152; }
    else                { t = 4; start = (bid - 35) * 2048; cnt = 2048; }
}

__global__ void quant_reduce(const float* __restrict__ Wc1,
                             const float* __restrict__ Wf1,
                             const float* __restrict__ Wf2,
                             const float* __restrict__ Wd,
                             const float* __restrict__ Wp) {
    __shared__ float red[256];
    int t, start, cnt;
    qmap(blockIdx.x, t, start, cnt);
    const float* src = (t==0) ? Wc1 : (t==1) ? Wf1 : (t==2) ? Wf2 : (t==3) ? Wd : Wp;

    float m = 0.f;
    for (int i = threadIdx.x; i < cnt; i += 256) m = fmaxf(m, fabsf(src[start + i]));
    red[threadIdx.x] = m;
    __syncthreads();
    for (int s = 128; s > 0; s >>= 1) {
        if (threadIdx.x < s) red[threadIdx.x] = fmaxf(red[threadIdx.x], red[threadIdx.x+s]);
        __syncthreads();
    }
    if (threadIdx.x == 0) atomicMax(&g_scmax[t], __float_as_uint(red[0]));
}

__global__ void quant_pack(const float* __restrict__ Wc1,
                           const float* __restrict__ Wf1,
                           const float* __restrict__ Wf2,
                           const float* __restrict__ Wd,
                           const float* __restrict__ Wp) {
    int t, start, cnt;
    qmap(blockIdx.x, t, start, cnt);
    const float* src = (t==0) ? Wc1 : (t==1) ? Wf1 : (t==2) ? Wf2 : (t==3) ? Wd : Wp;
    const float sc = fmaxf(__uint_as_float(g_scmax[t]), 1e-8f) / 127.f;

    for (int ii = threadIdx.x; ii < cnt; ii += 256) {
        int i = start + ii;
        float qi = rintf(src[i] / sc);
        qi = fminf(fmaxf(qi, -127.f), 127.f);
        float q = qi * sc;
        if (t == 0) {
            // UNSCALED integer; mma B layout: [chunk16][sub][ch][j], j = 2*(k%4) + (k%8)/4
            int o = i / CP, k = i % CP;
            int chunk = k >> 4, sub = (k >> 3) & 1, kk = k & 7;
            int j = 2*(kk & 3) + (kk >> 2);
            g_Wc1m[chunk*1536 + sub*768 + o*8 + j] = qi;
        }
        else if (t == 1) g_Wf1q[i] = q;
        else if (t == 2) { int o = i / 64,  k = i % 64; g_Wf2q[k*32 + o] = q; }
        else if (t == 3) { int c = i / 9,   j = i % 9;  g_Wdq[c*12 + j] = q; }
        else {
            // UNSCALED integer; mma B layout: [chunk8][o=80][j]
            int o = i / 128, c = i % 128;
            int chunk = c >> 3, kk = c & 7;
            int j = 2*(kk & 3) + (kk >> 2);
            g_Wpm[chunk*640 + o*8 + j] = qi;
        }
    }
}

// ---------------- 2) fused cor (tf32 mma.sync) + flo ------------------------------
__global__ __launch_bounds__(256, 2) void corflo_kernel(const float* __restrict__ corr,
                                                        const float* __restrict__ bc1,
                                                        const float* __restrict__ flow,
                                                        const float* __restrict__ bf1,
                                                        const float* __restrict__ bf2) {
    extern __shared__ __align__(16) float sm[];
    const int tid = threadIdx.x;

    if (blockIdx.x >= 1536) {
        // ---------------- flo path ----------------
        float* w1 = sm;            // 128
        float* b1 = sm + 128;      // 64
        float* w2 = sm + 192;      // 2048 [k][32]
        float* b2 = sm + 2240;     // 32
        for (int i = tid; i < 128;  i += 256) w1[i] = g_Wf1q[i];
        for (int i = tid; i < 64;   i += 256) b1[i] = bf1[i];
        for (int i = tid; i < 2048; i += 256) w2[i] = g_Wf2q[i];
        for (int i = tid; i < 32;   i += 256) b2[i] = bf2[i];
        __syncthreads();

        int p  = (blockIdx.x - 1536) * 256 + tid;
        int b  = p / HWW, hw = p % HWW;
        float fx = flow[(size_t)b * 2 * HWW + hw];
        float fy = flow[(size_t)b * 2 * HWW + HWW + hw];

        unsigned long long acc[16];
        #pragma unroll
        for (int q = 0; q < 16; q++) acc[q] = pack2(b2[2*q], b2[2*q+1]);

        #pragma unroll 4
        for (int j = 0; j < 64; j++) {
            float h = fmaxf(fmaf(fx, w1[2*j], fmaf(fy, w1[2*j+1], b1[j])), 0.f);
            unsigned long long hh = pack2(h, h);
            const ulonglong2* wv = reinterpret_cast<const ulonglong2*>(w2 + j*32);
            #pragma unroll
            for (int q = 0; q < 8; q++) {
                ulonglong2 a = wv[q];
                ffma2(acc[2*q],   hh, a.x);
                ffma2(acc[2*q+1], hh, a.y);
            }
        }

        const int y = hw >> 7, x = hw & 127;
        float* obase = g_cfp + ((size_t)(b*128 + 96) * PH + (y+1)) * PWS + x + 4;
        #pragma unroll
        for (int q = 0; q < 16; q++) {
            float2 f = unpack2(acc[q]);
            obase[(size_t)(2*q)   * PPL] = fmaxf(f.x, 0.f);
            obase[(size_t)(2*q+1) * PPL] = fmaxf(f.y, 0.f);
        }
        return;
    }

    // ---------------- cor path: tf32 mma, 16-k chunks ----------------
    float* bs  = sm;               // 96 bias
    float* Xs  = sm + 96;          // [2][16][136] = 4352
    float* Wsm = sm + 96 + 4352;   // [2][1536]    = 3072

    const int blk = blockIdx.x;            // 1536 = 16 b x 96 y
    const int b = blk / 96, y = blk % 96;
    const int w = tid >> 5, lane = tid & 31;
    const int gid = lane >> 2, tig = lane & 3;

    if (tid < 96) bs[tid] = bc1[tid];

    const float* cb = corr + (size_t)b * CP * HWW + (size_t)y * WW;
    uint32_t xs_s = (uint32_t)__cvta_generic_to_shared(Xs);
    uint32_t ws_s = (uint32_t)__cvta_generic_to_shared(Wsm);

    auto issue = [&](int c, int buf) {
        #pragma unroll
        for (int j = 0; j < 2; j++) {      // 16 rows x 32 float4 = 512
            int idx = tid + j*256;
            int row = idx >> 5, c4 = idx & 31;
            int k = c*16 + row;
            if (k < CP)
                cp16(xs_s + (uint32_t)((buf*(16*XROW) + row*XROW + c4*4)*4),
                     cb + (size_t)k * HWW + c4*4);
        }
        #pragma unroll
        for (int j = 0; j < 2; j++) {      // 1536 floats = 384 float4
            int idx = tid + j*256;
            if (idx < 384)
                cp16(ws_s + (uint32_t)((buf*1536 + idx*4)*4), g_Wc1m + c*1536 + idx*4);
        }
        asm volatile("cp.async.commit_group;");
    };

    issue(0, 0);

    float acc[48];                         // 12 ch-tiles x 4
    #pragma unroll
    for (int i = 0; i < 48; i++) acc[i] = 0.f;

    const int pxg = 16*w + gid;

    for (int c = 0; c < NCHK16; c++) {
        if (c + 1 < NCHK16) {
            issue(c + 1, (c + 1) & 1);
            asm volatile("cp.async.wait_group 1;");
        } else {
            asm volatile("cp.async.wait_group 0;");
        }
        __syncthreads();
        const float* xb = Xs  + (c & 1) * (16*XROW);
        const float* wb = Wsm + (c & 1) * 1536;

        #pragma unroll
        for (int s = 0; s < 2; s++) {
            uint32_t a0 = cvt_tf32(xb[(s*8 + tig    )*XROW + pxg    ]);
            uint32_t a1 = cvt_tf32(xb[(s*8 + tig    )*XROW + pxg + 8]);
            uint32_t a2 = cvt_tf32(xb[(s*8 + tig + 4)*XROW + pxg    ]);
            uint32_t a3 = cvt_tf32(xb[(s*8 + tig + 4)*XROW + pxg + 8]);
            const float* wsb = wb + s*768;
            #pragma unroll
            for (int t = 0; t < 12; t++) {
                unsigned long long bv =
                    *(const unsigned long long*)(wsb + (8*t + gid)*8 + 2*tig);
                uint32_t b0 = (uint32_t)bv, b1 = (uint32_t)(bv >> 32);
                mma_tf32(acc + 4*t, a0, a1, a2, a3, b0, b1);
            }
        }
        __syncthreads();                   // buffer consumed before re-issue
    }

    const float sc0 = fmaxf(__uint_as_float(g_scmax[0]), 1e-8f) / 127.f;
    const int x = 16*w + gid;
    #pragma unroll
    for (int t = 0; t < 12; t++) {
        int ch = 8*t + 2*tig;
        float* p0 = g_cfp + ((size_t)(b*128 + ch) * PH + (y+1)) * PWS + 4 + x;
        float* p1 = p0 + (size_t)PPL;      // ch+1 plane
        p0[0] = fmaxf(fmaf(sc0, acc[4*t+0], bs[ch]),   0.f);
        p1[0] = fmaxf(fmaf(sc0, acc[4*t+1], bs[ch+1]), 0.f);
        p0[8] = fmaxf(fmaf(sc0, acc[4*t+2], bs[ch]),   0.f);
        p1[8] = fmaxf(fmaf(sc0, acc[4*t+3], bs[ch+1]), 0.f);
    }
}

// ---------------- 3) fused dw3x3 (scalar) + pw 128->80 (tf32 mma) -----------------
// grid 768: pixel tile 64w x 4h = 256 px; 256 threads.
// Phase A: dw once per channel into dwb[8][264] (k-major = mma A-transposed).
// Phase B: warp = 32 px (2 m16 tiles) x 80 ch (10 n-tiles), 1 k8-step per chunk.
#define ITB 3456    // floats per halo buffer: 8 ch * 6 rows * 72
#define DWS 264     // dwb channel stride (8 mod 32 -> conflict-free A frags)
__global__ __launch_bounds__(256, 2) void dwpw_kernel(const float* __restrict__ flow,
                                                      const float* __restrict__ bp,
                                                      float* __restrict__ out) {
    extern __shared__ __align__(16) float sm2[];
    float* wpm = sm2;              // [16][640]  = 10240 (mma B, unscaled ints)
    float* wd  = wpm + 10240;      // [128][12]  = 1536
    float* bph = wd + 1536;        // 80
    float* it  = bph + 80;         // 2 x [8][6][72] = 6912
    float* dwb = it + 2*ITB;       // [8][264]   = 2112

    const int tid = threadIdx.x;
    for (int i = tid; i < 10240/4; i += 256) ((float4*)wpm)[i] = ((const float4*)g_Wpm)[i];
    for (int i = tid; i < 1536/4;  i += 256) ((float4*)wd)[i]  = ((const float4*)g_Wdq)[i];
    if (tid < 80) bph[tid] = bp[tid];

    const int blk = blockIdx.x;              // 768 tiles: 16b x 24y x 2x
    const int b = blk / 48, t0 = blk % 48;
    const int gy0 = (t0 >> 1) * 4, gx0 = (t0 & 1) * 64;
    const int cl = tid >> 5, l  = tid & 31;  // phase A: channel-in-chunk, lane
    const int w = tid >> 5, gid = l >> 2, tig = l & 3;   // phase B mma ids

    const float* cfb = g_cfp + (size_t)b * 128 * PPL;
    uint32_t it_s = (uint32_t)__cvta_generic_to_shared(it);

    auto issue = [&](int ch, int buf) {      // 8 ch x 6 rows x 18 float4 = 864
        const float* srcbase = cfb + (size_t)(ch*8) * PPL + gy0 * PWS + gx0;
        #pragma unroll
        for (int j = 0; j < 4; j++) {
            int idx = tid + j*256;
            if (idx < 864) {
                int c8 = idx / 108, rem = idx % 108;
                int ry = rem / 18,  rx  = rem % 18;
                cp16(it_s + (uint32_t)((buf*ITB + c8*432 + ry*72 + rx*4)*4),
                     srcbase + (size_t)c8*PPL + ry*PWS + rx*4);
            }
        }
        asm volatile("cp.async.commit_group;");
    };

    __syncthreads();                          // weights visible

    float acc[80];                            // [mt=2][t=10][4]
    #pragma unroll
    for (int i = 0; i < 80; i++) acc[i] = 0.f;

    issue(0, 0);

    for (int ch = 0; ch < 16; ch++) {
        if (ch + 1 < 16) {
            issue(ch + 1, (ch + 1) & 1);
            asm volatile("cp.async.wait_group 1;");
        } else {
            asm volatile("cp.async.wait_group 0;");
        }
        __syncthreads();                      // halo ready; dwb free
        const float* itb = it + (ch & 1) * ITB;

        // ---- phase A: depthwise once per channel ----
        {
            const float4* w4 = (const float4*)(wd + (ch*8 + cl)*12);
            float4 wa = w4[0], wb = w4[1];
            float  w8 = w4[2].x;
            #pragma unroll
            for (int hx = 0; hx < 2; hx++) {
                const int x = l + 32*hx;
                const float* tb = itb + cl*432 + x + 3;
                float d0, d1, d2, d3;
                {
                    float a0 = tb[0],   a1 = tb[1],   a2 = tb[2];
                    d0 = fmaf(a2, wa.z, fmaf(a1, wa.y, a0 * wa.x));
                    a0 = tb[72];  a1 = tb[73];  a2 = tb[74];
                    d0 = fmaf(a0, wa.w, d0); d0 = fmaf(a1, wb.x, d0); d0 = fmaf(a2, wb.y, d0);
                    d1 = fmaf(a2, wa.z, fmaf(a1, wa.y, a0 * wa.x));
                    a0 = tb[144]; a1 = tb[145]; a2 = tb[146];
                    d0 = fmaf(a0, wb.z, d0); d0 = fmaf(a1, wb.w, d0); d0 = fmaf(a2, w8, d0);
                    d1 = fmaf(a0, wa.w, d1); d1 = fmaf(a1, wb.x, d1); d1 = fmaf(a2, wb.y, d1);
                    d2 = fmaf(a2, wa.z, fmaf(a1, wa.y, a0 * wa.x));
                    a0 = tb[216]; a1 = tb[217]; a2 = tb[218];
                    d1 = fmaf(a0, wb.z, d1); d1 = fmaf(a1, wb.w, d1); d1 = fmaf(a2, w8, d1);
                    d2 = fmaf(a0, wa.w, d2); d2 = fmaf(a1, wb.x, d2); d2 = fmaf(a2, wb.y, d2);
                    d3 = fmaf(a2, wa.z, fmaf(a1, wa.y, a0 * wa.x));
                    a0 = tb[288]; a1 = tb[289]; a2 = tb[290];
                    d2 = fmaf(a0, wb.z, d2); d2 = fmaf(a1, wb.w, d2); d2 = fmaf(a2, w8, d2);
                    d3 = fmaf(a0, wa.w, d3); d3 = fmaf(a1, wb.x, d3); d3 = fmaf(a2, wb.y, d3);
                    a0 = tb[360]; a1 = tb[361]; a2 = tb[362];
                    d3 = fmaf(a0, wb.z, d3); d3 = fmaf(a1, wb.w, d3); d3 = fmaf(a2, w8, d3);
                }
                float* dst = dwb + cl*DWS + x;
                dst[0] = d0; dst[64] = d1; dst[128] = d2; dst[192] = d3;
            }
        }
        __syncthreads();                      // dwb visible

        // ---- phase B: tf32 mma, 1 k8-step ----
        const float* wchunk = wpm + ch*640;
        #pragma unroll
        for (int mt = 0; mt < 2; mt++) {
            const int px0 = 32*w + 16*mt;
            uint32_t a0 = cvt_tf32(dwb[ tig   *DWS + px0 + gid    ]);
            uint32_t a1 = cvt_tf32(dwb[ tig   *DWS + px0 + gid + 8]);
            uint32_t a2 = cvt_tf32(dwb[(tig+4)*DWS + px0 + gid    ]);
            uint32_t a3 = cvt_tf32(dwb[(tig+4)*DWS + px0 + gid + 8]);
            #pragma unroll
            for (int t = 0; t < 10; t++) {
                unsigned long long bv =
                    *(const unsigned long long*)(wchunk + (8*t + gid)*8 + 2*tig);
                uint32_t b0 = (uint32_t)bv, b1 = (uint32_t)(bv >> 32);
                mma_tf32(acc + mt*40 + 4*t, a0, a1, a2, a3, b0, b1);
            }
        }
    }

    // epilogue: out = relu(sc4 * acc + bias); lane covers 2x10x4 (px, ch) scalars
    const float sc4 = fmaxf(__uint_as_float(g_scmax[4]), 1e-8f) / 127.f;
    #pragma unroll
    for (int mt = 0; mt < 2; mt++) {
        const int pxa = 32*w + 16*mt + gid;
        const int ya = pxa >> 6, xa = pxa & 63;
        const int yb = (pxa + 8) >> 6, xb = (pxa + 8) & 63;
        float* oba = out + (size_t)b*82*HWW + (size_t)(gy0 + ya)*WW + gx0 + xa;
        float* obb = out + (size_t)b*82*HWW + (size_t)(gy0 + yb)*WW + gx0 + xb;
        #pragma unroll
        for (int t = 0; t < 10; t++) {
            const int ch = 8*t + 2*tig;
            const float b0v = bph[ch], b1v = bph[ch+1];
            oba[(size_t)ch     * HWW] = fmaxf(fmaf(sc4, acc[mt*40 + 4*t + 0], b0v), 0.f);
            oba[(size_t)(ch+1) * HWW] = fmaxf(fmaf(sc4, acc[mt*40 + 4*t + 1], b1v), 0.f);
            obb[(size_t)ch     * HWW] = fmaxf(fmaf(sc4, acc[mt*40 + 4*t + 2], b0v), 0.f);
            obb[(size_t)(ch+1) * HWW] = fmaxf(fmaf(sc4, acc[mt*40 + 4*t + 3], b1v), 0.f);
        }
    }
    if (tid < 64) {   // flow passthrough ch 80/81, float4
        const int p4 = tid * 4;
        const int y = gy0 + (p4 >> 6), x0 = gx0 + (p4 & 63);
        float4 f0 = *(const float4*)(flow + ((size_t)b*2 + 0)*HWW + (size_t)y*WW + x0);
        float4 f1 = *(const float4*)(flow + ((size_t)b*2 + 1)*HWW + (size_t)y*WW + x0);
        *(float4*)(out + ((size_t)b*82 + 80)*HWW + (size_t)y*WW + x0) = f0;
        *(float4*)(out + ((size_t)b*82 + 81)*HWW + (size_t)y*WW + x0) = f1;
    }
}

// ---------------- launch ----------------------------------------------------------
extern "C" void kernel_launch(void* const* d_in, const int* in_sizes, int n_in,
                              void* d_out, int out_size) {
    const float* flow = (const float*)d_in[0];
    const float* corr = (const float*)d_in[1];
    const float* Wc1  = (const float*)d_in[2];
    const float* bc1  = (const float*)d_in[3];
    const float* Wf1  = (const float*)d_in[4];
    const float* bf1  = (const float*)d_in[5];
    const float* Wf2  = (const float*)d_in[6];
    const float* bf2  = (const float*)d_in[7];
    const float* Wd   = (const float*)d_in[8];
    const float* Wp   = (const float*)d_in[9];
    const float* bp   = (const float*)d_in[10];
    float* out = (float*)d_out;

    const size_t cor_smem  = (size_t)(96 + 2*16*XROW + 2*1536) * sizeof(float);           // ~30 KB
    const size_t dwpw_smem = (size_t)(10240 + 1536 + 80 + 2*ITB + 8*DWS) * sizeof(float); // ~82 KB
    cudaFuncSetAttribute(corflo_kernel, cudaFuncAttributeMaxDynamicSharedMemorySize, (int)cor_smem);
    cudaFuncSetAttribute(dwpw_kernel,   cudaFuncAttributeMaxDynamicSharedMemorySize, (int)dwpw_smem);

    quant_reduce<<<40, 256>>>(Wc1, Wf1, Wf2, Wd, Wp);
    quant_pack<<<40, 256>>>(Wc1, Wf1, Wf2, Wd, Wp);
    corflo_kernel<<<1536 + 768, 256, cor_smem>>>(corr, bc1, flow, bf1, bf2);
    dwpw_kernel<<<768, 256, dwpw_smem>>>(flow, bp, out);
}